// round 2
// baseline (speedup 1.0000x reference)
#include <cuda_runtime.h>
#include <float.h>
#include <math.h>

// Problem constants
#define N_TOK   32768
#define DIM     512
#define NTYPE   26
#define PER     128
#define NCODE   (NTYPE*PER)     // 3328
#define SAMP    312             // 26 * 12
#define ND      (N_TOK*DIM)     // 16777216
#define TEMP    0.07f
#define COMMIT  0.25f

// -------- scratch (device globals; no allocation allowed) --------
__device__ float  g_xn[ND];            // normalized x
__device__ float  g_ne[NCODE*DIM];     // normalized embeddings
__device__ float  g_en2[NCODE];        // ||emb_j||^2 (raw input rows)
__device__ int    g_count[NTYPE];
__device__ int    g_offset[NTYPE];
__device__ int    g_cursor[NTYPE];
__device__ int    g_order[N_TOK];
__device__ int    g_idx[N_TOK];
__device__ float  g_se[SAMP*DIM];      // gathered normalized sampled rows
__device__ int    g_slab[SAMP];        // labels = sampled_idx / PER
__device__ double g_diff_acc;
__device__ double g_uloss_acc;

// -------- kernels --------
__global__ void k_init() {
    int t = threadIdx.x;
    if (t < NTYPE) g_count[t] = 0;
    if (t == 0) { g_diff_acc = 0.0; g_uloss_acc = 0.0; }
}

// block per row, 128 threads, each one float4
__global__ void k_norm_x(const float* __restrict__ x) {
    int row = blockIdx.x;
    int t = threadIdx.x;
    float4 a = ((const float4*)(x + (size_t)row * DIM))[t];
    float s = a.x*a.x + a.y*a.y + a.z*a.z + a.w*a.w;
    #pragma unroll
    for (int o = 16; o; o >>= 1) s += __shfl_xor_sync(0xffffffffu, s, o);
    __shared__ float ws[4];
    if ((t & 31) == 0) ws[t >> 5] = s;
    __syncthreads();
    float tot = ws[0] + ws[1] + ws[2] + ws[3];
    float inv = 1.0f / fmaxf(sqrtf(tot), 1e-12f);
    float4 o4 = make_float4(a.x*inv, a.y*inv, a.z*inv, a.w*inv);
    ((float4*)(g_xn + (size_t)row * DIM))[t] = o4;
}

// block per code row: norm2 + normalized row
__global__ void k_norm_emb(const float* __restrict__ emb) {
    int row = blockIdx.x;
    int t = threadIdx.x;
    float4 a = ((const float4*)(emb + (size_t)row * DIM))[t];
    float s = a.x*a.x + a.y*a.y + a.z*a.z + a.w*a.w;
    #pragma unroll
    for (int o = 16; o; o >>= 1) s += __shfl_xor_sync(0xffffffffu, s, o);
    __shared__ float ws[4];
    if ((t & 31) == 0) ws[t >> 5] = s;
    __syncthreads();
    float tot = ws[0] + ws[1] + ws[2] + ws[3];
    if (t == 0) g_en2[row] = tot;
    float inv = 1.0f / fmaxf(sqrtf(tot), 1e-12f);
    float4 o4 = make_float4(a.x*inv, a.y*inv, a.z*inv, a.w*inv);
    ((float4*)(g_ne + (size_t)row * DIM))[t] = o4;
}

__global__ void k_hist(const int* __restrict__ Q) {
    for (int i = blockIdx.x * blockDim.x + threadIdx.x; i < N_TOK;
         i += gridDim.x * blockDim.x)
        atomicAdd(&g_count[Q[i]], 1);
}

__global__ void k_scan() {
    int off = 0;
    for (int t = 0; t < NTYPE; t++) {
        g_offset[t] = off; g_cursor[t] = off; off += g_count[t];
    }
}

__global__ void k_scatter(const int* __restrict__ Q) {
    for (int i = blockIdx.x * blockDim.x + threadIdx.x; i < N_TOK;
         i += gridDim.x * blockDim.x) {
        int t = Q[i];
        int p = atomicAdd(&g_cursor[t], 1);
        g_order[p] = i;
    }
}

// GEMM + fused argmin. grid = (tiles, NTYPE), block = 256 (16x16), 8x8 thread tile.
// score_j = ||e_j||^2 - 2 * dot(xn_i, e_j); argmin with lowest-index tiebreak.
__global__ __launch_bounds__(256) void k_argmin(const float* __restrict__ emb) {
    int type = blockIdx.y;
    int cnt  = g_count[type];
    int row0 = blockIdx.x * 128;
    if (row0 >= cnt) return;
    int rows = min(128, cnt - row0);

    __shared__ float As[32][128];   // [k][token]
    __shared__ float Bs[32][128];   // [k][code]
    __shared__ int   toks[128];

    int tid = threadIdx.x;
    if (tid < 128) {
        int r = (tid < rows) ? tid : (rows - 1);
        toks[tid] = g_order[g_offset[type] + row0 + r];
    }
    __syncthreads();

    int lm = tid & 127;          // loader row (token/code index in tile)
    int kg = tid >> 7;           // 0..1
    const float* xrow = g_xn + (size_t)toks[lm] * DIM;
    const float* brow = emb + (size_t)(type * PER + lm) * DIM;

    int tx = tid & 15, ty = tid >> 4;

    float acc[8][8];
    #pragma unroll
    for (int i = 0; i < 8; i++)
        #pragma unroll
        for (int j = 0; j < 8; j++) acc[i][j] = 0.0f;

    for (int k0 = 0; k0 < DIM; k0 += 32) {
        #pragma unroll
        for (int g = 0; g < 4; g++) {
            int k4 = kg + g * 2;  // float4 index within the 32-wide chunk
            float4 va = *(const float4*)(xrow + k0 + k4 * 4);
            As[k4*4+0][lm] = va.x; As[k4*4+1][lm] = va.y;
            As[k4*4+2][lm] = va.z; As[k4*4+3][lm] = va.w;
            float4 vb = *(const float4*)(brow + k0 + k4 * 4);
            Bs[k4*4+0][lm] = vb.x; Bs[k4*4+1][lm] = vb.y;
            Bs[k4*4+2][lm] = vb.z; Bs[k4*4+3][lm] = vb.w;
        }
        __syncthreads();
        #pragma unroll
        for (int kk = 0; kk < 32; kk++) {
            float4 a0 = *(const float4*)&As[kk][ty*4];
            float4 a1 = *(const float4*)&As[kk][64 + ty*4];
            float4 b0 = *(const float4*)&Bs[kk][tx*4];
            float4 b1 = *(const float4*)&Bs[kk][64 + tx*4];
            float a[8] = {a0.x,a0.y,a0.z,a0.w,a1.x,a1.y,a1.z,a1.w};
            float b[8] = {b0.x,b0.y,b0.z,b0.w,b1.x,b1.y,b1.z,b1.w};
            #pragma unroll
            for (int i = 0; i < 8; i++)
                #pragma unroll
                for (int j = 0; j < 8; j++)
                    acc[i][j] = fmaf(a[i], b[j], acc[i][j]);
        }
        __syncthreads();
    }

    float en[8];
    #pragma unroll
    for (int j = 0; j < 8; j++) {
        int c = (j < 4) ? (tx*4 + j) : (64 + tx*4 + (j - 4));
        en[j] = g_en2[type * PER + c];
    }
    #pragma unroll
    for (int i = 0; i < 8; i++) {
        float best = FLT_MAX; int bc = 1 << 30;
        #pragma unroll
        for (int j = 0; j < 8; j++) {
            int c = (j < 4) ? (tx*4 + j) : (64 + tx*4 + (j - 4));
            float s = en[j] - 2.0f * acc[i][j];
            if (s < best || (s == best && c < bc)) { best = s; bc = c; }
        }
        #pragma unroll
        for (int o = 8; o; o >>= 1) {
            float s2 = __shfl_xor_sync(0xffffffffu, best, o);
            int   c2 = __shfl_xor_sync(0xffffffffu, bc,   o);
            if (s2 < best || (s2 == best && c2 < bc)) { best = s2; bc = c2; }
        }
        if (tx == 0) {
            int m = (i < 4) ? (ty*4 + i) : (64 + ty*4 + (i - 4));
            if (m < rows) g_idx[toks[m]] = type * PER + bc;
        }
    }
}

// out = xn + (q - xn); accumulate sum((q - xn)^2)
__global__ void k_finalize(float* __restrict__ out) {
    __shared__ float red[256];
    float local = 0.0f;
    int nt4 = ND / 4;
    for (int e4 = blockIdx.x * blockDim.x + threadIdx.x; e4 < nt4;
         e4 += gridDim.x * blockDim.x) {
        int i  = e4 >> 7;
        int d4 = e4 & 127;
        int id = g_idx[i];
        float4 q  = ((const float4*)(g_ne + (size_t)id * DIM))[d4];
        float4 xn = ((const float4*)g_xn)[e4];
        float4 df = make_float4(q.x - xn.x, q.y - xn.y, q.z - xn.z, q.w - xn.w);
        float4 o  = make_float4(xn.x + df.x, xn.y + df.y, xn.z + df.z, xn.w + df.w);
        ((float4*)out)[e4] = o;
        local += df.x*df.x + df.y*df.y + df.z*df.z + df.w*df.w;
    }
    red[threadIdx.x] = local;
    __syncthreads();
    for (int s = 128; s; s >>= 1) {
        if (threadIdx.x < s) red[threadIdx.x] += red[threadIdx.x + s];
        __syncthreads();
    }
    if (threadIdx.x == 0) atomicAdd(&g_diff_acc, (double)red[0]);
}

__global__ void k_gather_se(const int* __restrict__ samp) {
    int b = blockIdx.x;
    int s = samp[b];
    int t = threadIdx.x;  // 128 threads, 128 float4
    ((float4*)(g_se + (size_t)b * DIM))[t] =
        ((const float4*)(g_ne + (size_t)s * DIM))[t];
    if (t == 0) g_slab[b] = s / PER;
}

// block per sample row i; 8 warps stride over j; InfoNCE-style row loss
__global__ __launch_bounds__(256) void k_uloss() {
    int i = blockIdx.x;
    __shared__ float si[DIM];
    __shared__ float wsum[8], wpos[8];
    int tid = threadIdx.x;
    if (tid < 128) ((float4*)si)[tid] = ((const float4*)(g_se + (size_t)i * DIM))[tid];
    __syncthreads();
    int lab_i = g_slab[i];
    int w = tid >> 5, lane = tid & 31;
    float sum = 0.0f, pos = 0.0f;
    for (int j = w; j < SAMP; j += 8) {
        const float* vj = g_se + (size_t)j * DIM;
        float p = 0.0f;
        #pragma unroll 4
        for (int d = lane; d < DIM; d += 32) p = fmaf(si[d], vj[d], p);
        #pragma unroll
        for (int o = 16; o; o >>= 1) p += __shfl_xor_sync(0xffffffffu, p, o);
        if (lane == 0 && j != i) {
            float e = expf(p / TEMP);
            sum += e;
            if (g_slab[j] == lab_i) pos += e;
        }
    }
    if (lane == 0) { wsum[w] = sum; wpos[w] = pos; }
    __syncthreads();
    if (tid == 0) {
        float S = 0.0f, P = 0.0f;
        #pragma unroll
        for (int k = 0; k < 8; k++) { S += wsum[k]; P += wpos[k]; }
        atomicAdd(&g_uloss_acc, (double)(-logf(P / S)));
    }
}

__global__ void k_idx_tail(float* __restrict__ out) {
    int i = blockIdx.x * blockDim.x + threadIdx.x;
    if (i < N_TOK) out[ND + 2 + i] = (float)g_idx[i];
}

__global__ void k_scalars(float* __restrict__ out) {
    out[ND]     = (float)((1.0 + (double)COMMIT) * g_diff_acc / (double)ND);
    out[ND + 1] = (float)(g_uloss_acc / (double)SAMP);
}

// -------- launch --------
extern "C" void kernel_launch(void* const* d_in, const int* in_sizes, int n_in,
                              void* d_out, int out_size) {
    const float* x    = (const float*)d_in[0];
    const float* emb  = (const float*)d_in[1];
    const int*   Q    = (const int*)d_in[2];
    const int*   samp = (const int*)d_in[3];
    float* out = (float*)d_out;

    k_init<<<1, 32>>>();
    k_norm_x<<<N_TOK, 128>>>(x);
    k_norm_emb<<<NCODE, 128>>>(emb);
    k_hist<<<64, 256>>>(Q);
    k_scan<<<1, 1>>>();
    k_scatter<<<64, 256>>>(Q);
    dim3 g(256, NTYPE);
    k_argmin<<<g, 256>>>(emb);
    k_finalize<<<1184, 256>>>(out);
    k_gather_se<<<SAMP, 128>>>(samp);
    k_uloss<<<SAMP, 256>>>();
    if (out_size >= ND + 2 + N_TOK) {
        k_idx_tail<<<(N_TOK + 255) / 256, 256>>>(out);
        k_scalars<<<1, 1>>>(out);
    }
}

// round 3
// speedup vs baseline: 1.1667x; 1.1667x over previous
#include <cuda_runtime.h>
#include <float.h>
#include <math.h>

// Problem constants
#define N_TOK   32768
#define DIM     512
#define NTYPE   26
#define PER     128
#define NCODE   (NTYPE*PER)     // 3328
#define SAMP    312             // 26 * 12
#define ND      (N_TOK*DIM)     // 16777216
#define TEMP    0.07f
#define COMMIT  0.25f

// -------- scratch (device globals; no allocation allowed) --------
__device__ float  g_invn[N_TOK];       // 1/||x_i||
__device__ float  g_ne[NCODE*DIM];     // normalized embeddings
__device__ float  g_en2[NCODE];        // ||emb_j||^2 (raw input rows)
__device__ int    g_count[NTYPE];
__device__ int    g_offset[NTYPE];
__device__ int    g_cursor[NTYPE];
__device__ int    g_order[N_TOK];
__device__ int    g_idx[N_TOK];
__device__ int    g_work[512];         // (type<<8)|tile worklist
__device__ int    g_nwork;
__device__ int    g_ticket;
__device__ int    g_udone;
__device__ float  g_se[SAMP*DIM];      // gathered normalized sampled rows
__device__ int    g_slab[SAMP];
__device__ double g_diff_acc;
__device__ double g_uloss_acc;

// -------- kernels --------
__global__ void k_init() {
    int t = threadIdx.x;
    if (t < NTYPE) g_count[t] = 0;
    if (t == 0) {
        g_diff_acc = 0.0; g_uloss_acc = 0.0;
        g_ticket = 0; g_udone = 0;
    }
}

// one warp per row: inv norm only (no xn materialization)
__global__ void k_rownorm(const float* __restrict__ x) {
    int gw   = (blockIdx.x * blockDim.x + threadIdx.x) >> 5;
    int lane = threadIdx.x & 31;
    if (gw >= N_TOK) return;
    const float4* p = (const float4*)(x + (size_t)gw * DIM);
    float s = 0.0f;
    #pragma unroll
    for (int k = 0; k < 4; k++) {
        float4 a = p[lane + 32 * k];
        s += a.x*a.x + a.y*a.y + a.z*a.z + a.w*a.w;
    }
    #pragma unroll
    for (int o = 16; o; o >>= 1) s += __shfl_xor_sync(0xffffffffu, s, o);
    if (lane == 0) g_invn[gw] = 1.0f / fmaxf(sqrtf(s), 1e-12f);
}

// block per code row: norm2 + normalized row
__global__ void k_norm_emb(const float* __restrict__ emb) {
    int row = blockIdx.x;
    int t = threadIdx.x;
    float4 a = ((const float4*)(emb + (size_t)row * DIM))[t];
    float s = a.x*a.x + a.y*a.y + a.z*a.z + a.w*a.w;
    #pragma unroll
    for (int o = 16; o; o >>= 1) s += __shfl_xor_sync(0xffffffffu, s, o);
    __shared__ float ws[4];
    if ((t & 31) == 0) ws[t >> 5] = s;
    __syncthreads();
    float tot = ws[0] + ws[1] + ws[2] + ws[3];
    if (t == 0) g_en2[row] = tot;
    float inv = 1.0f / fmaxf(sqrtf(tot), 1e-12f);
    float4 o4 = make_float4(a.x*inv, a.y*inv, a.z*inv, a.w*inv);
    ((float4*)(g_ne + (size_t)row * DIM))[t] = o4;
}

// shared-memory histogram -> one global atomic per (block, type)
__global__ void k_hist(const int* __restrict__ Q) {
    __shared__ int h[NTYPE];
    if (threadIdx.x < NTYPE) h[threadIdx.x] = 0;
    __syncthreads();
    for (int i = blockIdx.x * blockDim.x + threadIdx.x; i < N_TOK;
         i += gridDim.x * blockDim.x)
        atomicAdd(&h[Q[i]], 1);
    __syncthreads();
    if (threadIdx.x < NTYPE && h[threadIdx.x])
        atomicAdd(&g_count[threadIdx.x], h[threadIdx.x]);
}

__global__ void k_scan() {
    int off = 0, nw = 0;
    for (int t = 0; t < NTYPE; t++) {
        g_offset[t] = off; g_cursor[t] = off;
        int c = g_count[t]; off += c;
        int tiles = (c + 127) / 128;
        for (int tt = 0; tt < tiles; tt++) g_work[nw++] = (t << 8) | tt;
    }
    g_nwork = nw;
}

// block-aggregated scatter: 1 global atomic per (block, type)
__global__ void k_scatter(const int* __restrict__ Q) {
    __shared__ int loc[NTYPE], base[NTYPE];
    int tid = threadIdx.x;
    if (tid < NTYPE) loc[tid] = 0;
    __syncthreads();
    int per = (N_TOK + gridDim.x - 1) / gridDim.x;
    int s = blockIdx.x * per;
    int e = min(s + per, N_TOK);
    for (int i = s + tid; i < e; i += blockDim.x)
        atomicAdd(&loc[Q[i]], 1);
    __syncthreads();
    if (tid < NTYPE) { base[tid] = atomicAdd(&g_cursor[tid], loc[tid]); loc[tid] = 0; }
    __syncthreads();
    for (int i = s + tid; i < e; i += blockDim.x) {
        int t = Q[i];
        g_order[base[t] + atomicAdd(&loc[t], 1)] = i;
    }
}

// Persistent GEMM + fused argmin + fused commit-loss + fused idx-tail.
// score_j = ||e_j||^2 - 2*invn*(x_i . e_j); q.xn = (en2 - best)/(2 sqrt(en2)).
__global__ __launch_bounds__(256, 2) void k_argmin(const float* __restrict__ x,
                                                   const float* __restrict__ emb,
                                                   float* __restrict__ out) {
    __shared__ float As[32][128];   // [k][token]
    __shared__ float Bs[32][128];   // [k][code]
    __shared__ int   toks[128];
    __shared__ float sinv[128];
    __shared__ int   s_work;
    __shared__ float red[256];

    int tid = threadIdx.x;
    int lm = tid & 127, kg = tid >> 7;
    int tx = tid & 15,  ty = tid >> 4;
    float local_loss = 0.0f;

    for (;;) {
        if (tid == 0) s_work = atomicAdd(&g_ticket, 1);
        __syncthreads();
        int w = s_work;
        if (w >= g_nwork) break;
        int wk   = g_work[w];
        int type = wk >> 8;
        int row0 = (wk & 255) * 128;
        int cnt  = g_count[type];
        int rows = min(128, cnt - row0);

        if (tid < 128) {
            int r = (tid < rows) ? tid : (rows - 1);
            int tk = g_order[g_offset[type] + row0 + r];
            toks[tid] = tk;
            sinv[tid] = g_invn[tk];
        }
        __syncthreads();

        const float* xrow = x   + (size_t)toks[lm] * DIM;
        const float* brow = emb + (size_t)(type * PER + lm) * DIM;

        float acc[8][8];
        #pragma unroll
        for (int i = 0; i < 8; i++)
            #pragma unroll
            for (int j = 0; j < 8; j++) acc[i][j] = 0.0f;

        for (int k0 = 0; k0 < DIM; k0 += 32) {
            #pragma unroll
            for (int g = 0; g < 4; g++) {
                int k4 = kg + g * 2;
                float4 va = *(const float4*)(xrow + k0 + k4 * 4);
                As[k4*4+0][lm] = va.x; As[k4*4+1][lm] = va.y;
                As[k4*4+2][lm] = va.z; As[k4*4+3][lm] = va.w;
                float4 vb = *(const float4*)(brow + k0 + k4 * 4);
                Bs[k4*4+0][lm] = vb.x; Bs[k4*4+1][lm] = vb.y;
                Bs[k4*4+2][lm] = vb.z; Bs[k4*4+3][lm] = vb.w;
            }
            __syncthreads();
            #pragma unroll
            for (int kk = 0; kk < 32; kk++) {
                float4 a0 = *(const float4*)&As[kk][ty*4];
                float4 a1 = *(const float4*)&As[kk][64 + ty*4];
                float4 b0 = *(const float4*)&Bs[kk][tx*4];
                float4 b1 = *(const float4*)&Bs[kk][64 + tx*4];
                float a[8] = {a0.x,a0.y,a0.z,a0.w,a1.x,a1.y,a1.z,a1.w};
                float b[8] = {b0.x,b0.y,b0.z,b0.w,b1.x,b1.y,b1.z,b1.w};
                #pragma unroll
                for (int i = 0; i < 8; i++)
                    #pragma unroll
                    for (int j = 0; j < 8; j++)
                        acc[i][j] = fmaf(a[i], b[j], acc[i][j]);
            }
            __syncthreads();
        }

        float en[8];
        #pragma unroll
        for (int j = 0; j < 8; j++) {
            int c = (j < 4) ? (tx*4 + j) : (64 + tx*4 + (j - 4));
            en[j] = g_en2[type * PER + c];
        }
        #pragma unroll
        for (int i = 0; i < 8; i++) {
            int m = (i < 4) ? (ty*4 + i) : (64 + ty*4 + (i - 4));
            float inv = sinv[m];
            float best = FLT_MAX; int bc = 1 << 30;
            #pragma unroll
            for (int j = 0; j < 8; j++) {
                int c = (j < 4) ? (tx*4 + j) : (64 + tx*4 + (j - 4));
                float s = en[j] - 2.0f * inv * acc[i][j];
                if (s < best || (s == best && c < bc)) { best = s; bc = c; }
            }
            #pragma unroll
            for (int o = 8; o; o >>= 1) {
                float s2 = __shfl_xor_sync(0xffffffffu, best, o);
                int   c2 = __shfl_xor_sync(0xffffffffu, bc,   o);
                if (s2 < best || (s2 == best && c2 < bc)) { best = s2; bc = c2; }
            }
            if (tx == 0 && m < rows) {
                int tok  = toks[m];
                int code = type * PER + bc;
                g_idx[tok] = code;
                out[ND + 2 + tok] = (float)code;
                float e2 = g_en2[code];
                // ||q - xn||^2 = 2 - 2*q.xn = 2 - (e2 - best)/sqrt(e2)
                local_loss += 2.0f - (e2 - best) / sqrtf(e2);
            }
        }
        __syncthreads();
    }

    red[tid] = local_loss;
    __syncthreads();
    for (int s = 128; s; s >>= 1) {
        if (tid < s) red[tid] += red[tid + s];
        __syncthreads();
    }
    if (tid == 0 && red[0] != 0.0f) atomicAdd(&g_diff_acc, (double)red[0]);
}

// out rows = ne[idx] (pure gather; ne is L2-resident)
__global__ void k_finalize(float* __restrict__ out) {
    int nt4 = ND / 4;
    for (int e4 = blockIdx.x * blockDim.x + threadIdx.x; e4 < nt4;
         e4 += gridDim.x * blockDim.x) {
        int i  = e4 >> 7;
        int d4 = e4 & 127;
        ((float4*)out)[e4] = ((const float4*)(g_ne + (size_t)g_idx[i] * DIM))[d4];
    }
}

__global__ void k_gather_se(const int* __restrict__ samp) {
    int b = blockIdx.x;
    int s = samp[b];
    int t = threadIdx.x;
    ((float4*)(g_se + (size_t)b * DIM))[t] =
        ((const float4*)(g_ne + (size_t)s * DIM))[t];
    if (t == 0) g_slab[b] = s / PER;
}

// block per sample row i; last block writes scalar outputs
__global__ __launch_bounds__(256) void k_uloss(float* __restrict__ out) {
    int i = blockIdx.x;
    __shared__ float si[DIM];
    __shared__ float wsum[8], wpos[8];
    int tid = threadIdx.x;
    if (tid < 128) ((float4*)si)[tid] = ((const float4*)(g_se + (size_t)i * DIM))[tid];
    __syncthreads();
    int lab_i = g_slab[i];
    int w = tid >> 5, lane = tid & 31;
    float sum = 0.0f, pos = 0.0f;
    for (int j = w; j < SAMP; j += 8) {
        const float* vj = g_se + (size_t)j * DIM;
        float p = 0.0f;
        #pragma unroll 4
        for (int d = lane; d < DIM; d += 32) p = fmaf(si[d], vj[d], p);
        #pragma unroll
        for (int o = 16; o; o >>= 1) p += __shfl_xor_sync(0xffffffffu, p, o);
        if (lane == 0 && j != i) {
            float e = expf(p / TEMP);
            sum += e;
            if (g_slab[j] == lab_i) pos += e;
        }
    }
    if (lane == 0) { wsum[w] = sum; wpos[w] = pos; }
    __syncthreads();
    if (tid == 0) {
        float S = 0.0f, P = 0.0f;
        #pragma unroll
        for (int k = 0; k < 8; k++) { S += wsum[k]; P += wpos[k]; }
        atomicAdd(&g_uloss_acc, (double)(-logf(P / S)));
        __threadfence();
        int d = atomicAdd(&g_udone, 1);
        if (d == SAMP - 1) {
            double u = atomicAdd(&g_uloss_acc, 0.0);  // acquire-ish read
            out[ND]     = (float)((1.0 + (double)COMMIT) * g_diff_acc / (double)ND);
            out[ND + 1] = (float)(u / (double)SAMP);
        }
    }
}

// -------- launch --------
extern "C" void kernel_launch(void* const* d_in, const int* in_sizes, int n_in,
                              void* d_out, int out_size) {
    const float* x    = (const float*)d_in[0];
    const float* emb  = (const float*)d_in[1];
    const int*   Q    = (const int*)d_in[2];
    const int*   samp = (const int*)d_in[3];
    float* out = (float*)d_out;

    k_init<<<1, 32>>>();
    k_rownorm<<<N_TOK / 8, 256>>>(x);
    k_norm_emb<<<NCODE, 128>>>(emb);
    k_hist<<<64, 256>>>(Q);
    k_scan<<<1, 1>>>();
    k_scatter<<<64, 256>>>(Q);
    k_argmin<<<296, 256>>>(x, emb, out);
    k_finalize<<<2048, 256>>>(out);
    k_gather_se<<<SAMP, 128>>>(samp);
    k_uloss<<<SAMP, 256>>>(out);
}